// round 17
// baseline (speedup 1.0000x reference)
// Round 17: issue-bound gather rebuilt: fp32 rows (no cvt), warp-per-node
// (32 thr x 8 floats), smem-staged (s,cf) uint2 pairs, j-unroll x2 via
// LDS.128. fp16 side-copies removed (fp16 gave -4us but added cvt instrs).
#include <cuda_runtime.h>
#include <stdint.h>

#define NN 50000
#define NE 800000
#define NG 64
#define IND 512
#define HIDD 256
#define OUTD 256
#define EPSV 0.1f

typedef unsigned int u32;

__device__ __forceinline__ int clampi(int v, int lo, int hi) {
    return v < lo ? lo : (v > hi ? hi : v);
}

// ---------------- scratch (device globals) ----------------
__device__ __align__(16) int   g_degi[NN];
__device__ __align__(16) int   g_rowstart[NN];
__device__ __align__(16) int   g_fill[NN];
__device__ __align__(16) int   g_bsum[64];
__device__ __align__(16) int   g_boff[64];
__device__ __align__(16) int   g_csrsrc[NE];
__device__ __align__(16) float g_dinv[NN];
__device__ __align__(16) float g_norm[NE];    // norm in CSR order
__device__ __align__(16) float g_al[NN];
__device__ __align__(16) float g_ar[NN];
__device__ __align__(16) float g_h[(size_t)NN * HIDD];
__device__ __align__(16) float g_h0[(size_t)NN * HIDD];
__device__ __align__(16) float g_agg[(size_t)NN * HIDD];
__device__ __align__(16) float g_sums[NG * OUTD];
__device__ __align__(16) float g_cnt[NG];

// ---------------- setup kernels ----------------
__global__ void zeroi_kernel() {
    int i = blockIdx.x * blockDim.x + threadIdx.x;
    if (i < NN) { g_degi[i] = 0; g_fill[i] = 0; }
    if (i < NG * OUTD) g_sums[i] = 0.f;
    if (i < NG) g_cnt[i] = 0.f;
}

__global__ void deg_kernel(const int* __restrict__ ei) {
    int e = blockIdx.x * blockDim.x + threadIdx.x;
    if (e < NE) {
        int d = clampi(ei[NE + e], 0, NN - 1);
        atomicAdd(&g_degi[d], 1);
    }
}

__global__ void dinv_kernel() {
    int i = blockIdx.x * blockDim.x + threadIdx.x;
    if (i < NN) {
        float d = (float)g_degi[i];
        g_dinv[i] = (d > 0.f) ? rsqrtf(fmaxf(d, 1.f)) : 0.f;
    }
}

// 3-phase scan
__global__ void scanA_kernel() {
    int tid = threadIdx.x;
    int i = blockIdx.x * 1024 + tid;
    int lane = tid & 31, w = tid >> 5;
    int v = (i < NN) ? g_degi[i] : 0;
    int incl = v;
#pragma unroll
    for (int o = 1; o < 32; o <<= 1) {
        int t = __shfl_up_sync(0xFFFFFFFFu, incl, o);
        if (lane >= o) incl += t;
    }
    __shared__ int wsum[32];
    if (lane == 31) wsum[w] = incl;
    __syncthreads();
    if (w == 0) {
        int x = wsum[lane];
        int xi = x;
#pragma unroll
        for (int o = 1; o < 32; o <<= 1) {
            int t = __shfl_up_sync(0xFFFFFFFFu, xi, o);
            if (lane >= o) xi += t;
        }
        wsum[lane] = xi;
    }
    __syncthreads();
    int woff = (w > 0) ? wsum[w - 1] : 0;
    if (i < NN) g_rowstart[i] = woff + incl - v;
    if (tid == 1023) g_bsum[blockIdx.x] = wsum[31];
}

__global__ void scanB_kernel(int nblocks) {
    int tid = threadIdx.x;
    int lane = tid & 31, w = tid >> 5;
    int v = (tid < nblocks) ? g_bsum[tid] : 0;
    int incl = v;
#pragma unroll
    for (int o = 1; o < 32; o <<= 1) {
        int t = __shfl_up_sync(0xFFFFFFFFu, incl, o);
        if (lane >= o) incl += t;
    }
    __shared__ int ws[2];
    if (lane == 31) ws[w] = incl;
    __syncthreads();
    int off = (w == 1) ? ws[0] : 0;
    if (tid < nblocks) g_boff[tid] = off + incl - v;
}

__global__ void scanC_kernel() {
    int i = blockIdx.x * 1024 + threadIdx.x;
    if (i < NN) g_rowstart[i] += g_boff[blockIdx.x];
}

__global__ void fill_kernel(const int* __restrict__ ei) {
    int e = blockIdx.x * blockDim.x + threadIdx.x;
    if (e < NE) {
        int s = clampi(ei[e], 0, NN - 1);
        int d = clampi(ei[NE + e], 0, NN - 1);
        int pos = g_rowstart[d] + atomicAdd(&g_fill[d], 1);
        pos = clampi(pos, 0, NE - 1);
        g_csrsrc[pos] = s;
        g_norm[pos] = g_dinv[s] * g_dinv[d];
    }
}

// ---------------- per-layer kernels ----------------
__global__ void attn_kernel(int sel,
                            const float* __restrict__ alw, const float* __restrict__ alb,
                            const float* __restrict__ arw, const float* __restrict__ arb,
                            int layer) {
    int node = (blockIdx.x * blockDim.x + threadIdx.x) >> 5;
    int lane = threadIdx.x & 31;
    if (node >= NN) return;
    const float* h = sel ? g_agg : g_h;
    const float* hp = h + (size_t)node * HIDD;
    const float* wl = alw + layer * HIDD;
    const float* wr = arw + layer * HIDD;
    float sl = 0.f, sr = 0.f;
#pragma unroll
    for (int i = 0; i < 8; i++) {
        float v = hp[lane + 32 * i];
        sl = fmaf(v, wl[lane + 32 * i], sl);
        sr = fmaf(v, wr[lane + 32 * i], sr);
    }
#pragma unroll
    for (int o = 16; o; o >>= 1) {
        sl += __shfl_xor_sync(0xFFFFFFFFu, sl, o);
        sr += __shfl_xor_sync(0xFFFFFFFFu, sr, o);
    }
    if (lane == 0) {
        g_al[node] = sl + alb[layer];
        g_ar[node] = sr + arb[layer];
    }
}

// gather: warp per node; thread owns 8 contiguous floats (lane*8).
// (s, cf) staged per 32-edge chunk into smem (uint2 pairs); inner loop
// reads 2 pairs per LDS.128 and does 4 LDG.128 + 16 FMA per 2 edges.
__global__ __launch_bounds__(256) void gather_kernel(int sel, int do_relu)
{
    __shared__ __align__(16) uint2 sh[8][32];
    int wid = threadIdx.x >> 5;
    int lane = threadIdx.x & 31;
    int node = blockIdx.x * 8 + wid;
    if (node >= NN) return;
    const float* h = sel ? g_agg : g_h;
    float* outp    = sel ? g_h   : g_agg;
    int beg = g_rowstart[node];
    int n = g_degi[node];
    float ar_d = g_ar[node];
    const int off = lane * 8;

    float4 accA = *(const float4*)(g_h0 + (size_t)node * HIDD + off);
    float4 accB = *(const float4*)(g_h0 + (size_t)node * HIDD + off + 4);
    accA.x *= EPSV; accA.y *= EPSV; accA.z *= EPSV; accA.w *= EPSV;
    accB.x *= EPSV; accB.y *= EPSV; accB.z *= EPSV; accB.w *= EPSV;

    for (int base = 0; base < n; base += 32) {
        int cnt = min(32, n - base);
        if (lane < cnt) {
            int s = __ldg(&g_csrsrc[beg + base + lane]);
            float nrm = __ldg(&g_norm[beg + base + lane]);
            float cf = nrm * tanhf(__ldg(&g_al[s]) + ar_d);
            sh[wid][lane] = make_uint2((u32)s, __float_as_uint(cf));
        }
        __syncwarp();
        int j = 0;
        for (; j + 2 <= cnt; j += 2) {
            uint4 pr = *(const uint4*)&sh[wid][j];   // 2 (s,cf) pairs
            const float* r0 = h + (size_t)pr.x * HIDD + off;
            const float* r1 = h + (size_t)pr.z * HIDD + off;
            float cf0 = __uint_as_float(pr.y);
            float cf1 = __uint_as_float(pr.w);
            float4 v0a = __ldg((const float4*)r0);
            float4 v0b = __ldg((const float4*)(r0 + 4));
            float4 v1a = __ldg((const float4*)r1);
            float4 v1b = __ldg((const float4*)(r1 + 4));
            accA.x = fmaf(cf0, v0a.x, accA.x); accA.y = fmaf(cf0, v0a.y, accA.y);
            accA.z = fmaf(cf0, v0a.z, accA.z); accA.w = fmaf(cf0, v0a.w, accA.w);
            accB.x = fmaf(cf0, v0b.x, accB.x); accB.y = fmaf(cf0, v0b.y, accB.y);
            accB.z = fmaf(cf0, v0b.z, accB.z); accB.w = fmaf(cf0, v0b.w, accB.w);
            accA.x = fmaf(cf1, v1a.x, accA.x); accA.y = fmaf(cf1, v1a.y, accA.y);
            accA.z = fmaf(cf1, v1a.z, accA.z); accA.w = fmaf(cf1, v1a.w, accA.w);
            accB.x = fmaf(cf1, v1b.x, accB.x); accB.y = fmaf(cf1, v1b.y, accB.y);
            accB.z = fmaf(cf1, v1b.z, accB.z); accB.w = fmaf(cf1, v1b.w, accB.w);
        }
        if (j < cnt) {
            uint2 pr = sh[wid][j];
            const float* r0 = h + (size_t)pr.x * HIDD + off;
            float cf0 = __uint_as_float(pr.y);
            float4 v0a = __ldg((const float4*)r0);
            float4 v0b = __ldg((const float4*)(r0 + 4));
            accA.x = fmaf(cf0, v0a.x, accA.x); accA.y = fmaf(cf0, v0a.y, accA.y);
            accA.z = fmaf(cf0, v0a.z, accA.z); accA.w = fmaf(cf0, v0a.w, accA.w);
            accB.x = fmaf(cf0, v0b.x, accB.x); accB.y = fmaf(cf0, v0b.y, accB.y);
            accB.z = fmaf(cf0, v0b.z, accB.z); accB.w = fmaf(cf0, v0b.w, accB.w);
        }
        __syncwarp();
    }
    if (do_relu) {
        accA.x = fmaxf(accA.x, 0.f); accA.y = fmaxf(accA.y, 0.f);
        accA.z = fmaxf(accA.z, 0.f); accA.w = fmaxf(accA.w, 0.f);
        accB.x = fmaxf(accB.x, 0.f); accB.y = fmaxf(accB.y, 0.f);
        accB.z = fmaxf(accB.z, 0.f); accB.w = fmaxf(accB.w, 0.f);
    }
    *(float4*)(outp + (size_t)node * HIDD + off)     = accA;
    *(float4*)(outp + (size_t)node * HIDD + off + 4) = accB;
}

// ---------------- bf16 3-term tensor-core GEMM ----------------
__device__ __forceinline__ u32 cvt_bf2(float lo, float hi) {
    u32 d;
    asm("cvt.rn.bf16x2.f32 %0, %1, %2;" : "=r"(d) : "f"(hi), "f"(lo));
    return d;
}
__device__ __forceinline__ void split2(float lo, float hi, u32& big, u32& sml) {
    big = cvt_bf2(lo, hi);
    float blo = __uint_as_float(big << 16);
    float bhi = __uint_as_float(big & 0xFFFF0000u);
    sml = cvt_bf2(lo - blo, hi - bhi);
}
__device__ __forceinline__ void mma_bf16(float* c, const u32* a, const u32* b) {
    asm volatile(
        "mma.sync.aligned.m16n8k16.row.col.f32.bf16.bf16.f32 "
        "{%0,%1,%2,%3}, {%4,%5,%6,%7}, {%8,%9}, {%0,%1,%2,%3};"
        : "+f"(c[0]), "+f"(c[1]), "+f"(c[2]), "+f"(c[3])
        : "r"(a[0]), "r"(a[1]), "r"(a[2]), "r"(a[3]), "r"(b[0]), "r"(b[1]));
}

template <int CFG>
__global__ __launch_bounds__(256) void bfgemm_kernel(
    const float* __restrict__ Aext, const float* __restrict__ B,
    const float* __restrict__ bias, float* __restrict__ Cext,
    int M, int K, int N)
{
    const float* A = (CFG == 0) ? Aext : (const float*)g_h;
    float* C       = (CFG == 0) ? (float*)g_h : Cext;

    __shared__ u32 Abig[128][20], Asml[128][20];
    __shared__ u32 Bbig[8][72],  Bsml[8][72];

    const int tid  = threadIdx.x;
    const int lane = tid & 31;
    const int warp = tid >> 5;
    const int wm = warp >> 1;
    const int wn = warp & 1;
    const int g   = lane >> 2;
    const int tig = lane & 3;
    const int row0 = blockIdx.x * 128;
    const int col0 = blockIdx.y * 64;
    const int rw = wm * 32;
    const int cw = wn * 32;

    float acc[2][4][4];
#pragma unroll
    for (int mt = 0; mt < 2; mt++)
#pragma unroll
        for (int nt = 0; nt < 4; nt++)
#pragma unroll
            for (int r = 0; r < 4; r++) acc[mt][nt][r] = 0.f;

    const int r_a  = tid >> 2;
    const int kq_a = tid & 3;
    const bool va0 = (row0 + r_a) < M;
    const bool va1 = (row0 + r_a + 64) < M;
    const int p_b  = tid >> 4;
    const int nq_b = tid & 15;

    const int KT = K >> 4;
    float4 pa0, pa1, pb0, pb1;
    {
        pa0 = va0 ? *(const float4*)(A + (size_t)(row0 + r_a) * K + kq_a * 4)
                  : make_float4(0.f, 0.f, 0.f, 0.f);
        pa1 = va1 ? *(const float4*)(A + (size_t)(row0 + r_a + 64) * K + kq_a * 4)
                  : make_float4(0.f, 0.f, 0.f, 0.f);
        if (tid < 128) {
            pb0 = *(const float4*)(B + (size_t)(2 * p_b) * N + col0 + nq_b * 4);
            pb1 = *(const float4*)(B + (size_t)(2 * p_b + 1) * N + col0 + nq_b * 4);
        }
    }

    for (int kt = 0; kt < KT; kt++) {
        {
            u32 b0, s0, b1, s1;
            split2(pa0.x, pa0.y, b0, s0);
            split2(pa0.z, pa0.w, b1, s1);
            Abig[r_a][2 * kq_a] = b0;  Abig[r_a][2 * kq_a + 1] = b1;
            Asml[r_a][2 * kq_a] = s0;  Asml[r_a][2 * kq_a + 1] = s1;
            split2(pa1.x, pa1.y, b0, s0);
            split2(pa1.z, pa1.w, b1, s1);
            Abig[r_a + 64][2 * kq_a] = b0;  Abig[r_a + 64][2 * kq_a + 1] = b1;
            Asml[r_a + 64][2 * kq_a] = s0;  Asml[r_a + 64][2 * kq_a + 1] = s1;
        }
        if (tid < 128) {
            const float* e0 = &pb0.x;
            const float* e1 = &pb1.x;
#pragma unroll
            for (int j = 0; j < 4; j++) {
                u32 bg, sm;
                split2(e0[j], e1[j], bg, sm);
                Bbig[p_b][4 * nq_b + j] = bg;
                Bsml[p_b][4 * nq_b + j] = sm;
            }
        }
        __syncthreads();

        if (kt + 1 < KT) {
            int k0n = (kt + 1) * 16;
            pa0 = va0 ? *(const float4*)(A + (size_t)(row0 + r_a) * K + k0n + kq_a * 4)
                      : make_float4(0.f, 0.f, 0.f, 0.f);
            pa1 = va1 ? *(const float4*)(A + (size_t)(row0 + r_a + 64) * K + k0n + kq_a * 4)
                      : make_float4(0.f, 0.f, 0.f, 0.f);
            if (tid < 128) {
                pb0 = *(const float4*)(B + (size_t)(k0n + 2 * p_b) * N + col0 + nq_b * 4);
                pb1 = *(const float4*)(B + (size_t)(k0n + 2 * p_b + 1) * N + col0 + nq_b * 4);
            }
        }

        u32 ab[2][4], as[2][4];
#pragma unroll
        for (int mt = 0; mt < 2; mt++) {
            int rb = rw + mt * 16;
            ab[mt][0] = Abig[rb + g][tig];       as[mt][0] = Asml[rb + g][tig];
            ab[mt][1] = Abig[rb + g + 8][tig];   as[mt][1] = Asml[rb + g + 8][tig];
            ab[mt][2] = Abig[rb + g][tig + 4];   as[mt][2] = Asml[rb + g][tig + 4];
            ab[mt][3] = Abig[rb + g + 8][tig + 4]; as[mt][3] = Asml[rb + g + 8][tig + 4];
        }
        u32 bb[4][2], bs[4][2];
#pragma unroll
        for (int nt = 0; nt < 4; nt++) {
            int cb = cw + nt * 8 + g;
            bb[nt][0] = Bbig[tig][cb];      bs[nt][0] = Bsml[tig][cb];
            bb[nt][1] = Bbig[tig + 4][cb];  bs[nt][1] = Bsml[tig + 4][cb];
        }
#pragma unroll
        for (int mt = 0; mt < 2; mt++)
#pragma unroll
            for (int nt = 0; nt < 4; nt++) {
                mma_bf16(acc[mt][nt], ab[mt], bb[nt]);
                mma_bf16(acc[mt][nt], ab[mt], bs[nt]);
                mma_bf16(acc[mt][nt], as[mt], bb[nt]);
            }
        __syncthreads();
    }

#pragma unroll
    for (int nt = 0; nt < 4; nt++) {
        int ccol = col0 + cw + nt * 8 + 2 * tig;
        float2 bbv = *(const float2*)&bias[ccol];
#pragma unroll
        for (int mt = 0; mt < 2; mt++) {
            int r1 = row0 + rw + mt * 16 + g;
            int r2 = r1 + 8;
            float2 o0 = make_float2(acc[mt][nt][0] + bbv.x, acc[mt][nt][1] + bbv.y);
            float2 o1 = make_float2(acc[mt][nt][2] + bbv.x, acc[mt][nt][3] + bbv.y);
            if (r1 < M) {
                *(float2*)(C + (size_t)r1 * N + ccol) = o0;
                if (CFG == 0) *(float2*)((float*)g_h0 + (size_t)r1 * N + ccol) = o0;
            }
            if (r2 < M) {
                *(float2*)(C + (size_t)r2 * N + ccol) = o1;
                if (CFG == 0) *(float2*)((float*)g_h0 + (size_t)r2 * N + ccol) = o1;
            }
        }
    }
}

// ---------------- pooling ----------------
#define STRIP 200
__global__ __launch_bounds__(256) void pool_kernel(
    const float* __restrict__ nr, const int* __restrict__ batch)
{
    int c = threadIdx.x;
    int n0 = blockIdx.x * STRIP;
    int n1 = min(n0 + STRIP, NN);
    if (n0 >= NN) return;
    int curg = clampi(batch[n0], 0, NG - 1);
    float acc = 0.f;
    int cnt_local = 0;
    for (int n = n0; n < n1; n++) {
        int g = clampi(batch[n], 0, NG - 1);
        if (g != curg) {
            atomicAdd(&g_sums[curg * OUTD + c], acc);
            if (c == 0) atomicAdd(&g_cnt[curg], (float)cnt_local);
            acc = 0.f; cnt_local = 0; curg = g;
        }
        acc += nr[(size_t)n * OUTD + c];
        cnt_local++;
    }
    atomicAdd(&g_sums[curg * OUTD + c], acc);
    if (c == 0) atomicAdd(&g_cnt[curg], (float)cnt_local);
}

__global__ void finalize_kernel(float* __restrict__ out) {
    int i = blockIdx.x * blockDim.x + threadIdx.x;
    if (i < NG * OUTD) out[i] = g_sums[i] / fmaxf(g_cnt[i >> 8], 1.0f);
}

// ---------------- launch ----------------
extern "C" void kernel_launch(void* const* d_in, const int* in_sizes, int n_in,
                              void* d_out, int out_size) {
    const float *x = 0, *W_in = 0, *b_in = 0, *alw = 0, *alb = 0,
                *arw = 0, *arb = 0, *W_out = 0, *b_out = 0;
    const int *ei = 0, *batch = 0;
    for (int i = 0; i < n_in; i++) {
        long long s = in_sizes[i];
        const void* p = d_in[i];
        switch (s) {
            case 25600000LL: x     = (const float*)p; break;
            case 1600000LL:  ei    = (const int*)p;   break;
            case 50000LL:    batch = (const int*)p;   break;
            case 131072LL:   W_in  = (const float*)p; break;
            case 65536LL:    W_out = (const float*)p; break;
            case 512LL:      if (!alw) alw = (const float*)p; else arw = (const float*)p; break;
            case 2LL:        if (!alb) alb = (const float*)p; else arb = (const float*)p; break;
            case 256LL:      if (!b_in) b_in = (const float*)p; else b_out = (const float*)p; break;
            default: break;
        }
    }
    float* out = (float*)d_out;

    const int T = 256;
    const int SB = (NN + 1023) / 1024;

    zeroi_kernel<<<(NN + T - 1) / T, T>>>();
    deg_kernel<<<(NE + T - 1) / T, T>>>(ei);
    dinv_kernel<<<(NN + T - 1) / T, T>>>();
    scanA_kernel<<<SB, 1024>>>();
    scanB_kernel<<<1, 64>>>(SB);
    scanC_kernel<<<SB, 1024>>>();
    fill_kernel<<<(NE + T - 1) / T, T>>>(ei);

    dim3 g1((NN + 127) / 128, HIDD / 64);
    bfgemm_kernel<0><<<g1, 256>>>(x, W_in, b_in, nullptr, NN, IND, HIDD);

    // layer 0 (coef fused into gather)
    attn_kernel<<<(NN + 7) / 8, T>>>(0, alw, alb, arw, arb, 0);
    gather_kernel<<<(NN + 7) / 8, 256>>>(0, 1);

    // layer 1
    attn_kernel<<<(NN + 7) / 8, T>>>(1, alw, alb, arw, arb, 1);
    gather_kernel<<<(NN + 7) / 8, 256>>>(1, 0);

    dim3 g2((NN + 127) / 128, OUTD / 64);
    bfgemm_kernel<1><<<g2, 256>>>(nullptr, W_out, b_out, out, NN, HIDD, OUTD);

    pool_kernel<<<(NN + STRIP - 1) / STRIP, 256>>>(out, batch);
    finalize_kernel<<<(NG * OUTD + T - 1) / T, T>>>(out + (size_t)NN * OUTD);
}